// round 3
// baseline (speedup 1.0000x reference)
#include <cuda_runtime.h>
#include <stdint.h>

#define NN 65536
#define DD 256
#define KK 4096

#define BM 128
#define BN 128
#define BK 32
#define AP 132   // padded pitch for transposed A tile (rows dim)
#define BP 132   // padded pitch for transposed B tile (cols dim)

// scratch (static __device__ — no allocation)
__device__ float g_acc[KK * DD];   // running numerator: c0*centers + seg_sum
__device__ float g_cntf[KK];       // running denominator: c0 + seg_cnt
__device__ float g_c2[KK];         // ||center||^2
__device__ float g_loss;

// ---------------------------------------------------------------------------
// init: g_acc = counts*centers, g_cntf = counts, g_c2 = sum(c^2), loss = 0
// ---------------------------------------------------------------------------
__global__ void init_kernel(const float* __restrict__ centers,
                            const int* __restrict__ counts) {
    int k = blockIdx.x;
    int d = threadIdx.x;             // 256 threads
    float c = centers[(size_t)k * DD + d];
    float cnt = (float)counts[k];
    g_acc[(size_t)k * DD + d] = cnt * c;

    __shared__ float red[8];
    float v = c * c;
    #pragma unroll
    for (int off = 16; off > 0; off >>= 1)
        v += __shfl_down_sync(0xffffffffu, v, off);
    if ((d & 31) == 0) red[d >> 5] = v;
    __syncthreads();
    if (d == 0) {
        float s = 0.f;
        #pragma unroll
        for (int w = 0; w < 8; ++w) s += red[w];
        g_c2[k] = s;
        g_cntf[k] = cnt;
        if (k == 0) g_loss = 0.f;
    }
}

// ---------------------------------------------------------------------------
// fused GEMM + argmin + loss + segment-sum scatter
// block = 128 rows; loops over all 4096 centers in 128-col tiles.
// ---------------------------------------------------------------------------
__global__ void __launch_bounds__(256, 1)
assign_kernel(const float* __restrict__ emb,
              const float* __restrict__ centers,
              float* __restrict__ labels_out) {
    extern __shared__ float sm[];
    float* At    = sm;                       // [256][AP] transposed A (k-major)
    float* Bst   = At + 256 * AP;            // [2][BK][BP] transposed B, dbl buf
    float* x2s   = Bst + 2 * BK * BP;        // [128]
    float* loss_s = x2s + BM;                // [128]
    int*   lab_s  = (int*)(loss_s + BM);     // [128]

    const int tid = threadIdx.x;
    const int tx = tid & 15;
    const int ty = tid >> 4;
    const int row0 = blockIdx.x * BM;

    if (tid < BM) x2s[tid] = 0.f;

    // load A transposed: At[k][r] = emb[row0+r][k]  (coalesced global float4)
    #pragma unroll
    for (int it = 0; it < 32; ++it) {
        int f = it * 256 + tid;
        int r = f >> 6;            // 0..127
        int k4 = f & 63;           // 0..63
        float4 v = *reinterpret_cast<const float4*>(
            &emb[(size_t)(row0 + r) * DD + k4 * 4]);
        At[(k4 * 4 + 0) * AP + r] = v.x;
        At[(k4 * 4 + 1) * AP + r] = v.y;
        At[(k4 * 4 + 2) * AP + r] = v.z;
        At[(k4 * 4 + 3) * AP + r] = v.w;
    }
    __syncthreads();

    // x2 per row (2 threads/row, conflict-free lanes over r)
    {
        int r = tid & 127;
        int kbase = (tid >> 7) * 128;
        float s = 0.f;
        #pragma unroll 8
        for (int k = 0; k < 128; ++k) {
            float a = At[(kbase + k) * AP + r];
            s = fmaf(a, a, s);
        }
        atomicAdd(&x2s[r], s);
    }

    float bestv[8];
    int   bestj[8];
    #pragma unroll
    for (int i = 0; i < 8; ++i) { bestv[i] = 3.4e38f; bestj[i] = 0; }

    for (int j0 = 0; j0 < KK; j0 += BN) {
        float acc[8][8];
        #pragma unroll
        for (int i = 0; i < 8; ++i)
            #pragma unroll
            for (int j = 0; j < 8; ++j) acc[i][j] = 0.f;

        float4 ldreg[4];
        // prologue: load k-tile 0 of this column tile into buf 0
        #pragma unroll
        for (int q = 0; q < 4; ++q) {
            int f = q * 256 + tid;
            int jj = f >> 3, kk4 = f & 7;
            ldreg[q] = *reinterpret_cast<const float4*>(
                &centers[(size_t)(j0 + jj) * DD + kk4 * 4]);
        }
        #pragma unroll
        for (int q = 0; q < 4; ++q) {
            int f = q * 256 + tid;
            int jj = f >> 3, kk4 = f & 7;
            Bst[(kk4 * 4 + 0) * BP + jj] = ldreg[q].x;
            Bst[(kk4 * 4 + 1) * BP + jj] = ldreg[q].y;
            Bst[(kk4 * 4 + 2) * BP + jj] = ldreg[q].z;
            Bst[(kk4 * 4 + 3) * BP + jj] = ldreg[q].w;
        }
        __syncthreads();

        #pragma unroll 1
        for (int t = 0; t < DD / BK; ++t) {
            const int buf = t & 1;
            if (t < DD / BK - 1) {
                int k0n = (t + 1) * BK;
                #pragma unroll
                for (int q = 0; q < 4; ++q) {
                    int f = q * 256 + tid;
                    int jj = f >> 3, kk4 = f & 7;
                    ldreg[q] = *reinterpret_cast<const float4*>(
                        &centers[(size_t)(j0 + jj) * DD + k0n + kk4 * 4]);
                }
            }
            const float* Bp = Bst + buf * BK * BP;
            #pragma unroll
            for (int kk = 0; kk < BK; ++kk) {
                const int kabs = t * BK + kk;
                const float4 a0 = *reinterpret_cast<const float4*>(&At[kabs * AP + ty * 4]);
                const float4 a1 = *reinterpret_cast<const float4*>(&At[kabs * AP + 64 + ty * 4]);
                const float4 b0 = *reinterpret_cast<const float4*>(&Bp[kk * BP + tx * 4]);
                const float4 b1 = *reinterpret_cast<const float4*>(&Bp[kk * BP + 64 + tx * 4]);
                const float a[8] = {a0.x, a0.y, a0.z, a0.w, a1.x, a1.y, a1.z, a1.w};
                const float b[8] = {b0.x, b0.y, b0.z, b0.w, b1.x, b1.y, b1.z, b1.w};
                #pragma unroll
                for (int i = 0; i < 8; ++i)
                    #pragma unroll
                    for (int j = 0; j < 8; ++j)
                        acc[i][j] = fmaf(a[i], b[j], acc[i][j]);
            }
            if (t < DD / BK - 1) {
                float* Bw = Bst + (buf ^ 1) * BK * BP;
                #pragma unroll
                for (int q = 0; q < 4; ++q) {
                    int f = q * 256 + tid;
                    int jj = f >> 3, kk4 = f & 7;
                    Bw[(kk4 * 4 + 0) * BP + jj] = ldreg[q].x;
                    Bw[(kk4 * 4 + 1) * BP + jj] = ldreg[q].y;
                    Bw[(kk4 * 4 + 2) * BP + jj] = ldreg[q].z;
                    Bw[(kk4 * 4 + 3) * BP + jj] = ldreg[q].w;
                }
            }
            __syncthreads();
        }

        // epilogue: t = c2 - 2*dot ; running argmin
        #pragma unroll
        for (int j = 0; j < 8; ++j) {
            const int col = j0 + ((j < 4) ? (tx * 4 + j) : (64 + tx * 4 + j - 4));
            const float c2v = __ldg(&g_c2[col]);
            #pragma unroll
            for (int i = 0; i < 8; ++i) {
                float v = fmaf(-2.f, acc[i][j], c2v);
                if (v < bestv[i]) { bestv[i] = v; bestj[i] = col; }
            }
        }
    }

    // cross-thread argmin reduce over the 16 tx lanes (width-16 groups)
    #pragma unroll
    for (int i = 0; i < 8; ++i) {
        float v = bestv[i];
        int j = bestj[i];
        #pragma unroll
        for (int off = 8; off > 0; off >>= 1) {
            float ov = __shfl_down_sync(0xffffffffu, v, off, 16);
            int   oj = __shfl_down_sync(0xffffffffu, j, off, 16);
            if (ov < v || (ov == v && oj < j)) { v = ov; j = oj; }
        }
        if (tx == 0) {
            const int r = (i < 4) ? (ty * 4 + i) : (64 + ty * 4 + i - 4);
            lab_s[r] = j;
            loss_s[r] = x2s[r] + v;         // = ||x - c_j||^2
            labels_out[row0 + r] = (float)j;
        }
    }
    __syncthreads();

    // block loss -> one atomic
    if (tid == 0) {
        float s = 0.f;
        #pragma unroll 4
        for (int r = 0; r < BM; ++r) s += loss_s[r];
        atomicAdd(&g_loss, s);
    }
    // counts
    if (tid < BM) atomicAdd(&g_cntf[lab_s[tid]], 1.0f);
    // segment-sum scatter: rows are in smem (At), coalesced REDG per row
    for (int r = 0; r < BM; ++r) {
        const int lab = lab_s[r];
        atomicAdd(&g_acc[(size_t)lab * DD + tid], At[tid * AP + r]);
    }
}

// ---------------------------------------------------------------------------
// finalize: centers / counts / loss into output buffer
// layout: [labels N][centers K*D][counts K][loss 1], all fp32
// ---------------------------------------------------------------------------
__global__ void finalize_kernel(float* __restrict__ out) {
    int k = blockIdx.x;
    int d = threadIdx.x;
    float cnt = g_cntf[k];
    out[(size_t)NN + (size_t)k * DD + d] = g_acc[(size_t)k * DD + d] / cnt;
    if (d == 0) out[(size_t)NN + (size_t)KK * DD + k] = cnt;  // exact int in fp32
    if (k == 0 && d == 0)
        out[(size_t)NN + (size_t)KK * DD + KK] = g_loss / (float)NN;
}

// ---------------------------------------------------------------------------
extern "C" void kernel_launch(void* const* d_in, const int* in_sizes, int n_in,
                              void* d_out, int out_size) {
    const float* emb     = (const float*)d_in[0];
    const float* centers = (const float*)d_in[1];
    const int*   counts  = (const int*)d_in[2];
    float* out = (float*)d_out;

    const int smem_bytes = (256 * AP + 2 * BK * BP + BM + BM + BM) * 4;
    cudaFuncSetAttribute(assign_kernel,
                         cudaFuncAttributeMaxDynamicSharedMemorySize, smem_bytes);

    init_kernel<<<KK, 256>>>(centers, counts);
    assign_kernel<<<NN / BM, 256, smem_bytes>>>(emb, centers, out);
    finalize_kernel<<<KK, DD>>>(out);
}

// round 5
// speedup vs baseline: 1.5756x; 1.5756x over previous
#include <cuda_runtime.h>
#include <stdint.h>

#define NN 65536
#define DD 256
#define KK 4096
#define BM 128
#define BN 128
#define FCAP 65536
#define MARGIN 0.125f

// device scratch (no allocation)
__device__ float g_acc[KK * DD];
__device__ float g_cntf[KK];
__device__ float g_c2[KK];
__device__ float g_cb[KK * DD];   // tf32-RN rounded centers
__device__ float g_loss;
__device__ int g_flagcnt;
__device__ int g_flagrows[FCAP];

__device__ __forceinline__ float round_tf32(float x) {
    uint32_t r; asm("cvt.rn.tf32.f32 %0, %1;" : "=r"(r) : "f"(x));
    return __uint_as_float(r);
}

#define MMA8(d, a, b)                                                          \
    asm volatile("mma.sync.aligned.m16n8k8.row.col.f32.tf32.tf32.f32 "        \
        "{%0,%1,%2,%3}, {%4,%5,%6,%7}, {%8,%9}, {%0,%1,%2,%3};"               \
        : "+f"((d)[0]), "+f"((d)[1]), "+f"((d)[2]), "+f"((d)[3])              \
        : "r"((a).x), "r"((a).y), "r"((a).z), "r"((a).w),                     \
          "r"((b)[0]), "r"((b)[1]))

// ------------------------------- init -------------------------------
__global__ void init_kernel(const float* __restrict__ centers,
                            const int* __restrict__ counts) {
    int k = blockIdx.x, d = threadIdx.x;
    float c = centers[(size_t)k * DD + d];
    float cnt = (float)counts[k];
    g_acc[(size_t)k * DD + d] = cnt * c;
    g_cb[(size_t)k * DD + d] = round_tf32(c);
    __shared__ float red[8];
    float v = c * c;
    #pragma unroll
    for (int o = 16; o > 0; o >>= 1) v += __shfl_down_sync(~0u, v, o);
    if ((d & 31) == 0) red[d >> 5] = v;
    __syncthreads();
    if (d == 0) {
        float s = 0.f;
        #pragma unroll
        for (int w = 0; w < 8; ++w) s += red[w];
        g_c2[k] = s; g_cntf[k] = cnt;
        if (k == 0) { g_loss = 0.f; g_flagcnt = 0; }
    }
}

// --------------------- tf32 mma.sync GEMM + argmin ---------------------
// smem: AF 32768 floats (A fragment-major), BT 2*32*132 floats, RED 1536 floats
#define AF_FLOATS 32768
#define BT_FLOATS (2 * 32 * 132)
#define RED_FLOATS (3 * 512)
#define GEMM_SMEM ((AF_FLOATS + BT_FLOATS + RED_FLOATS) * 4)

__global__ void __launch_bounds__(256, 1)
gemm_kernel(const float* __restrict__ emb, float* __restrict__ labels_out) {
    extern __shared__ float sm[];
    float* AF = sm;
    float* BT = sm + AF_FLOATS;
    float* RB1 = sm + AF_FLOATS + BT_FLOATS;   // [4][128]
    int*   RI1 = (int*)(RB1 + 512);            // [4][128]
    float* RB2 = RB1 + 1024;                   // [4][128]

    const int tid = threadIdx.x, lane = tid & 31, wid = tid >> 5;
    const int warp_m = wid >> 2, warp_n = wid & 3;
    const int g = lane >> 2, t = lane & 3;
    const int row0 = blockIdx.x * BM;

    // ---- stage A in fragment-major layout (tf32-rounded) ----
    #pragma unroll 4
    for (int it = 0; it < 32; ++it) {
        int i = it * 256 + tid;
        int m = i >> 6, kq = i & 63;
        float4 v = *reinterpret_cast<const float4*>(emb + (size_t)(row0 + m) * DD + kq * 4);
        v.x = round_tf32(v.x); v.y = round_tf32(v.y);
        v.z = round_tf32(v.z); v.w = round_tf32(v.w);
        int s = kq >> 1, q = kq & 1, mt = m >> 4, r = m & 15;
        int base = ((s * 8 + mt) * 32 + (r & 7) * 4) * 4 + (r >> 3) + 2 * q;
        AF[base] = v.x; AF[base + 4] = v.y; AF[base + 8] = v.z; AF[base + 12] = v.w;
    }

    float b1[8], b2[8]; int i1[8];
    #pragma unroll
    for (int s = 0; s < 8; ++s) { b1[s] = 3.4e38f; b2[s] = 3.4e38f; i1[s] = 0; }

    __syncthreads();

    #pragma unroll 1
    for (int j0 = 0; j0 < KK; j0 += BN) {
        float acc[4][4][4];
        #pragma unroll
        for (int a = 0; a < 4; ++a)
            #pragma unroll
            for (int b = 0; b < 4; ++b)
                #pragma unroll
                for (int e = 0; e < 4; ++e) acc[a][b][e] = 0.f;

        float4 ld[4];
        // prologue: chunk 0
        #pragma unroll
        for (int q = 0; q < 4; ++q) {
            int i = q * 256 + tid, j = i >> 3, k4 = i & 7;
            ld[q] = *reinterpret_cast<const float4*>(g_cb + (size_t)(j0 + j) * DD + k4 * 4);
        }
        #pragma unroll
        for (int q = 0; q < 4; ++q) {
            int i = q * 256 + tid, j = i >> 3, k4 = i & 7;
            BT[(k4 * 4 + 0) * 132 + j] = ld[q].x;
            BT[(k4 * 4 + 1) * 132 + j] = ld[q].y;
            BT[(k4 * 4 + 2) * 132 + j] = ld[q].z;
            BT[(k4 * 4 + 3) * 132 + j] = ld[q].w;
        }
        __syncthreads();

        #pragma unroll 1
        for (int ch = 0; ch < 8; ++ch) {
            const float* Bb = BT + (ch & 1) * 4224;
            if (ch < 7) {
                #pragma unroll
                for (int q = 0; q < 4; ++q) {
                    int i = q * 256 + tid, j = i >> 3, k4 = i & 7;
                    ld[q] = *reinterpret_cast<const float4*>(
                        g_cb + (size_t)(j0 + j) * DD + (ch + 1) * 32 + k4 * 4);
                }
            }
            #pragma unroll
            for (int s4 = 0; s4 < 4; ++s4) {
                const int sg = ch * 4 + s4;
                uint4 a[4];
                #pragma unroll
                for (int mt = 0; mt < 4; ++mt)
                    a[mt] = *reinterpret_cast<const uint4*>(
                        AF + ((sg * 8 + warp_m * 4 + mt) * 32 + lane) * 4);
                uint32_t bb[4][2];
                #pragma unroll
                for (int nt = 0; nt < 4; ++nt) {
                    int col = warp_n * 32 + nt * 8 + g;
                    bb[nt][0] = __float_as_uint(Bb[(s4 * 8 + t) * 132 + col]);
                    bb[nt][1] = __float_as_uint(Bb[(s4 * 8 + t + 4) * 132 + col]);
                }
                #pragma unroll
                for (int mt = 0; mt < 4; ++mt)
                    #pragma unroll
                    for (int nt = 0; nt < 4; ++nt)
                        MMA8(acc[mt][nt], a[mt], bb[nt]);
            }
            if (ch < 7) {
                float* Bw = BT + ((ch & 1) ^ 1) * 4224;
                #pragma unroll
                for (int q = 0; q < 4; ++q) {
                    int i = q * 256 + tid, j = i >> 3, k4 = i & 7;
                    Bw[(k4 * 4 + 0) * 132 + j] = ld[q].x;
                    Bw[(k4 * 4 + 1) * 132 + j] = ld[q].y;
                    Bw[(k4 * 4 + 2) * 132 + j] = ld[q].z;
                    Bw[(k4 * 4 + 3) * 132 + j] = ld[q].w;
                }
            }
            __syncthreads();
        }

        // epilogue: v = c2 - 2*dot, running (best1, idx, best2) per row-slot
        #pragma unroll
        for (int nt = 0; nt < 4; ++nt) {
            const int cb = j0 + warp_n * 32 + nt * 8 + 2 * t;
            const float c20 = __ldg(&g_c2[cb]);
            const float c21 = __ldg(&g_c2[cb + 1]);
            #pragma unroll
            for (int mt = 0; mt < 4; ++mt) {
                #pragma unroll
                for (int h = 0; h < 2; ++h) {
                    const int s = mt * 2 + h;
                    float v0 = fmaf(-2.f, acc[mt][nt][2 * h + 0], c20);
                    float v1 = fmaf(-2.f, acc[mt][nt][2 * h + 1], c21);
                    if (v0 < b1[s]) { b2[s] = b1[s]; b1[s] = v0; i1[s] = cb; }
                    else if (v0 < b2[s]) b2[s] = v0;
                    if (v1 < b1[s]) { b2[s] = b1[s]; b1[s] = v1; i1[s] = cb + 1; }
                    else if (v1 < b2[s]) b2[s] = v1;
                }
            }
        }
    }

    // reduce across t-lanes (width 4)
    #pragma unroll
    for (int s = 0; s < 8; ++s) {
        float xb1 = b1[s], xb2 = b2[s]; int xi1 = i1[s];
        #pragma unroll
        for (int off = 2; off > 0; off >>= 1) {
            float ob1 = __shfl_down_sync(~0u, xb1, off, 4);
            int   oi1 = __shfl_down_sync(~0u, xi1, off, 4);
            float ob2 = __shfl_down_sync(~0u, xb2, off, 4);
            bool ylt = (ob1 < xb1) || (ob1 == xb1 && oi1 < xi1);
            float oth = ylt ? xb1 : ob1;
            xb2 = fminf(fminf(xb2, ob2), oth);
            if (ylt) { xb1 = ob1; xi1 = oi1; }
        }
        if (t == 0) {
            int row = warp_m * 64 + (s >> 1) * 16 + (s & 1) * 8 + g;
            RB1[warp_n * 128 + row] = xb1;
            RI1[warp_n * 128 + row] = xi1;
            RB2[warp_n * 128 + row] = xb2;
        }
    }
    __syncthreads();

    if (tid < 128) {
        float fb1 = RB1[tid], fb2 = RB2[tid]; int fi1 = RI1[tid];
        #pragma unroll
        for (int w = 1; w < 4; ++w) {
            float ob1 = RB1[w * 128 + tid], ob2 = RB2[w * 128 + tid];
            int oi1 = RI1[w * 128 + tid];
            bool ylt = (ob1 < fb1) || (ob1 == fb1 && oi1 < fi1);
            float oth = ylt ? fb1 : ob1;
            fb2 = fminf(fminf(fb2, ob2), oth);
            if (ylt) { fb1 = ob1; fi1 = oi1; }
        }
        labels_out[row0 + tid] = (float)fi1;
        if (fb2 - fb1 < MARGIN) {
            int p = atomicAdd(&g_flagcnt, 1);
            if (p < FCAP) g_flagrows[p] = row0 + tid;
        }
    }
}

// ---------------- exact fp32 rescore of flagged rows ----------------
__global__ void __launch_bounds__(256)
rescore_kernel(const float* __restrict__ emb, const float* __restrict__ centers,
               float* __restrict__ labels_out) {
    __shared__ float sx[8 * 260];
    __shared__ float wb1[64];
    __shared__ int wi1[64];
    const int tid = threadIdx.x, lane = tid & 31, w = tid >> 5;
    int cnt = g_flagcnt; if (cnt > FCAP) cnt = FCAP;
    for (int base = blockIdx.x * 8; base < cnt; base += gridDim.x * 8) {
        __syncthreads();
        for (int i = tid; i < 8 * 256; i += 256) {
            int r = i >> 8, k = i & 255;
            sx[r * 260 + k] = (base + r < cnt)
                ? emb[(size_t)g_flagrows[base + r] * DD + k] : 0.f;
        }
        __syncthreads();
        float b1 = 3.4e38f; int i1 = 0;
        #pragma unroll 1
        for (int c = w; c < KK; c += 8) {
            float cv[8];
            #pragma unroll
            for (int q = 0; q < 8; ++q)
                cv[q] = __ldg(centers + (size_t)c * DD + lane + 32 * q);
            float p[8];
            #pragma unroll
            for (int r = 0; r < 8; ++r) {
                float s = 0.f;
                #pragma unroll
                for (int q = 0; q < 8; ++q)
                    s = fmaf(cv[q], sx[r * 260 + lane + 32 * q], s);
                p[r] = s;
            }
            #pragma unroll
            for (int off = 16; off > 0; off >>= 1)
                #pragma unroll
                for (int r = 0; r < 8; ++r)
                    p[r] += __shfl_xor_sync(~0u, p[r], off);
            if (lane < 8) {
                float v = fmaf(-2.f, p[lane], __ldg(&g_c2[c]));
                if (v < b1) { b1 = v; i1 = c; }
            }
        }
        if (lane < 8) { wb1[w * 8 + lane] = b1; wi1[w * 8 + lane] = i1; }
        __syncthreads();
        if (tid < 8) {
            float fb = wb1[tid]; int fi = wi1[tid];
            #pragma unroll
            for (int ww = 1; ww < 8; ++ww) {
                float ob = wb1[ww * 8 + tid]; int oi = wi1[ww * 8 + tid];
                if (ob < fb || (ob == fb && oi < fi)) { fb = ob; fi = oi; }
            }
            if (base + tid < cnt)
                labels_out[g_flagrows[base + tid]] = (float)fi;
        }
        __syncthreads();
    }
}

// -------- exact loss + segment sums + counts (final labels) --------
__global__ void __launch_bounds__(256)
scatter_kernel(const float* __restrict__ emb, const float* __restrict__ centers,
               const float* __restrict__ labels) {
    const int t = threadIdx.x;
    const int r0 = blockIdx.x * 64;
    float lsum = 0.f;
    #pragma unroll 1
    for (int r = 0; r < 64; ++r) {
        const int row = r0 + r;
        const int lab = (int)labels[row];
        float x = emb[(size_t)row * DD + t];
        float c = __ldg(&centers[(size_t)lab * DD + t]);
        float d = x - c;
        lsum = fmaf(d, d, lsum);
        atomicAdd(&g_acc[(size_t)lab * DD + t], x);
        if (t == 0) atomicAdd(&g_cntf[lab], 1.0f);
    }
    __shared__ float red[8];
    #pragma unroll
    for (int o = 16; o > 0; o >>= 1) lsum += __shfl_down_sync(~0u, lsum, o);
    if ((t & 31) == 0) red[t >> 5] = lsum;
    __syncthreads();
    if (t == 0) {
        float s = 0.f;
        #pragma unroll
        for (int w = 0; w < 8; ++w) s += red[w];
        atomicAdd(&g_loss, s);
    }
}

__global__ void finalize_kernel(float* __restrict__ out) {
    int k = blockIdx.x, d = threadIdx.x;
    float cnt = g_cntf[k];
    out[(size_t)NN + (size_t)k * DD + d] = g_acc[(size_t)k * DD + d] / cnt;
    if (d == 0) out[(size_t)NN + (size_t)KK * DD + k] = cnt;
    if (k == 0 && d == 0) out[(size_t)NN + (size_t)KK * DD + KK] = g_loss / (float)NN;
}

extern "C" void kernel_launch(void* const* d_in, const int* in_sizes, int n_in,
                              void* d_out, int out_size) {
    const float* emb     = (const float*)d_in[0];
    const float* centers = (const float*)d_in[1];
    const int*   counts  = (const int*)d_in[2];
    float* out = (float*)d_out;

    cudaFuncSetAttribute(gemm_kernel, cudaFuncAttributeMaxDynamicSharedMemorySize, GEMM_SMEM);

    init_kernel<<<KK, 256>>>(centers, counts);
    gemm_kernel<<<NN / BM, 256, GEMM_SMEM>>>(emb, out);
    rescore_kernel<<<256, 256>>>(emb, centers, out);
    scatter_kernel<<<NN / 64, 256>>>(emb, centers, out);
    finalize_kernel<<<KK, DD>>>(out);
}

// round 6
// speedup vs baseline: 3.0830x; 1.9567x over previous
#include <cuda_runtime.h>
#include <cuda_bf16.h>
#include <stdint.h>

#define NN 65536
#define DD 256
#define KK 4096
#define BM 128
#define BN 128
#define FCAP 65536
#define M2 1.8f

__device__ float g_acc[KK * DD];
__device__ float g_cntf[KK];
__device__ float g_c2[KK];
__device__ unsigned g_cbt[128 * KK];       // bf16x2 centers, k2-major: [k2][n]
__device__ float g_loss;
__device__ int g_flagcnt;
__device__ int g_flagrows[FCAP];
__device__ unsigned g_cand[(size_t)FCAP * 48];

__device__ __forceinline__ unsigned pack_bf2(float lo, float hi) {
    unsigned r; asm("cvt.rn.bf16x2.f32 %0, %1, %2;" : "=r"(r) : "f"(hi), "f"(lo));
    return r;
}

#define MMA16(d, a, b0, b1)                                                    \
    asm volatile("mma.sync.aligned.m16n8k16.row.col.f32.bf16.bf16.f32 "       \
        "{%0,%1,%2,%3}, {%4,%5,%6,%7}, {%8,%9}, {%0,%1,%2,%3};"               \
        : "+f"((d)[0]), "+f"((d)[1]), "+f"((d)[2]), "+f"((d)[3])              \
        : "r"((a).x), "r"((a).y), "r"((a).z), "r"((a).w), "r"(b0), "r"(b1))

// ------------------------------- init -------------------------------
__global__ void init_kernel(const float* __restrict__ centers,
                            const int* __restrict__ counts) {
    int k = blockIdx.x, d = threadIdx.x;
    __shared__ float cs[DD];
    float c = centers[(size_t)k * DD + d];
    float cnt = (float)counts[k];
    g_acc[(size_t)k * DD + d] = cnt * c;
    cs[d] = c;
    __shared__ float red[8];
    float v = c * c;
    #pragma unroll
    for (int o = 16; o > 0; o >>= 1) v += __shfl_down_sync(~0u, v, o);
    if ((d & 31) == 0) red[d >> 5] = v;
    __syncthreads();
    if (d < 128)
        g_cbt[(size_t)d * KK + k] = pack_bf2(cs[2 * d], cs[2 * d + 1]);
    if (d == 0) {
        float s = 0.f;
        #pragma unroll
        for (int w = 0; w < 8; ++w) s += red[w];
        g_c2[k] = s; g_cntf[k] = cnt;
        if (k == 0) { g_loss = 0.f; g_flagcnt = 0; }
    }
}

// ------------------- bf16 mma.sync GEMM + top-3 argmin -------------------
// smem u32 layout: A frags [0, 16384), B dbl buf [16384, 16384+2*2176)
#define B_OFF 16384
#define BBUF 2176
#define SMEM_U32 (B_OFF + 2 * BBUF)
#define GEMM_SMEM (SMEM_U32 * 4)

__global__ void __launch_bounds__(256, 1)
gemm_kernel(const float* __restrict__ emb, float* __restrict__ labels_out) {
    extern __shared__ unsigned smu[];
    const int tid = threadIdx.x, lane = tid & 31, wid = tid >> 5;
    const int warp_m = wid >> 2, warp_n = wid & 3;
    const int g = lane >> 2, t = lane & 3;
    const int row0 = blockIdx.x * BM;

    // ---- stage A: bf16 fragment-major ----
    #pragma unroll 4
    for (int it = 0; it < 32; ++it) {
        int i = it * 256 + tid;
        int m = i >> 6, kq = i & 63;
        float4 v = *reinterpret_cast<const float4*>(emb + (size_t)(row0 + m) * DD + kq * 4);
        unsigned w0 = pack_bf2(v.x, v.y), w1 = pack_bf2(v.z, v.w);
        int rr = m & 15, mt = m >> 4;
        #pragma unroll
        for (int hh = 0; hh < 2; ++hh) {
            int k2 = 2 * kq + hh;
            int sg = k2 >> 3, kw = k2 & 7;
            int L = (rr & 7) * 4 + (kw & 3);
            int j = (rr >> 3) + 2 * (kw >> 2);
            smu[((sg * 8 + mt) * 32 + L) * 4 + j] = hh ? w1 : w0;
        }
    }

    float sv1[8], sv2[8], sv3[8]; int si1[8], si2[8], si3[8];
    #pragma unroll
    for (int s = 0; s < 8; ++s) {
        sv1[s] = sv2[s] = sv3[s] = 3.4e38f;
        si1[s] = si2[s] = si3[s] = 0;
    }
    __syncthreads();

    const int pk2r = tid >> 4, pn8 = (tid & 15) * 8;

    #pragma unroll 1
    for (int tile = 0; tile < KK / BN; ++tile) {
        const int j0 = tile * BN;
        float acc[4][4][4];
        #pragma unroll
        for (int a = 0; a < 4; ++a)
            #pragma unroll
            for (int b = 0; b < 4; ++b)
                #pragma unroll
                for (int e = 0; e < 4; ++e) acc[a][b][e] = 0.f;

        // prologue: chunk 0 -> buf 0
        uint4 p0, p1;
        {
            const uint4* src = reinterpret_cast<const uint4*>(
                g_cbt + (size_t)pk2r * KK + j0 + pn8);
            p0 = src[0]; p1 = src[1];
            uint4* dst = reinterpret_cast<uint4*>(smu + B_OFF + pk2r * 136 + pn8);
            dst[0] = p0; dst[1] = p1;
        }
        __syncthreads();

        #pragma unroll 1
        for (int ch = 0; ch < 8; ++ch) {
            const int buf = ch & 1;
            if (ch < 7) {
                const uint4* src = reinterpret_cast<const uint4*>(
                    g_cbt + (size_t)((ch + 1) * 16 + pk2r) * KK + j0 + pn8);
                p0 = src[0]; p1 = src[1];
            }
            const unsigned* Bb = smu + B_OFF + buf * BBUF;
            #pragma unroll
            for (int s4 = 0; s4 < 2; ++s4) {
                const int sgg = ch * 2 + s4;
                uint4 a[4];
                #pragma unroll
                for (int mt = 0; mt < 4; ++mt)
                    a[mt] = *(reinterpret_cast<const uint4*>(smu) +
                              ((sgg * 8 + warp_m * 4 + mt) * 32 + lane));
                unsigned bb[4][2];
                #pragma unroll
                for (int nt = 0; nt < 4; ++nt) {
                    int col = warp_n * 32 + nt * 8 + g;
                    bb[nt][0] = Bb[(s4 * 8 + t) * 136 + col];
                    bb[nt][1] = Bb[(s4 * 8 + t + 4) * 136 + col];
                }
                #pragma unroll
                for (int mt = 0; mt < 4; ++mt)
                    #pragma unroll
                    for (int nt = 0; nt < 4; ++nt)
                        MMA16(acc[mt][nt], a[mt], bb[nt][0], bb[nt][1]);
            }
            if (ch < 7) {
                uint4* dst = reinterpret_cast<uint4*>(
                    smu + B_OFF + (buf ^ 1) * BBUF + pk2r * 136 + pn8);
                dst[0] = p0; dst[1] = p1;
            }
            __syncthreads();
        }

        // per-tile epilogue: v = c2 - 2*dot, top-3 insert per row-slot
        #pragma unroll
        for (int nt = 0; nt < 4; ++nt) {
            const int cb = j0 + warp_n * 32 + nt * 8 + 2 * t;
            const float c20 = __ldg(&g_c2[cb]);
            const float c21 = __ldg(&g_c2[cb + 1]);
            #pragma unroll
            for (int mt = 0; mt < 4; ++mt) {
                #pragma unroll
                for (int h = 0; h < 2; ++h) {
                    const int s = mt * 2 + h;
                    #pragma unroll
                    for (int e = 0; e < 2; ++e) {
                        float v = fmaf(-2.f, acc[mt][nt][2 * h + e], e ? c21 : c20);
                        int c = cb + e;
                        if (v < sv3[s]) {
                            if (v < sv1[s]) {
                                sv3[s] = sv2[s]; si3[s] = si2[s];
                                sv2[s] = sv1[s]; si2[s] = si1[s];
                                sv1[s] = v; si1[s] = c;
                            } else if (v < sv2[s]) {
                                sv3[s] = sv2[s]; si3[s] = si2[s];
                                sv2[s] = v; si2[s] = c;
                            } else { sv3[s] = v; si3[s] = c; }
                        }
                    }
                }
            }
        }
    }

    // ---- merge: alias reduction arrays over A smem region ----
    __syncthreads();
    float* V1 = (float*)smu;            // [16][128]
    float* V2 = V1 + 2048;
    float* V3 = V2 + 2048;
    int*   I1 = (int*)(V3 + 2048);
    int*   I2 = I1 + 2048;
    int*   I3 = I2 + 2048;
    const int slot = warp_n * 4 + t;
    #pragma unroll
    for (int s = 0; s < 8; ++s) {
        int row = warp_m * 64 + (s >> 1) * 16 + (s & 1) * 8 + g;
        V1[slot * 128 + row] = sv1[s]; I1[slot * 128 + row] = si1[s];
        V2[slot * 128 + row] = sv2[s]; I2[slot * 128 + row] = si2[s];
        V3[slot * 128 + row] = sv3[s]; I3[slot * 128 + row] = si3[s];
    }
    __syncthreads();

    if (tid < 128) {
        float v1 = 3.4e38f, v2 = 3.4e38f; int i1 = 1 << 30;
        #pragma unroll
        for (int s = 0; s < 16; ++s) {
            float a1 = V1[s * 128 + tid], a2 = V2[s * 128 + tid], a3 = V3[s * 128 + tid];
            int   b1 = I1[s * 128 + tid];
            bool lt = (a1 < v1) || (a1 == v1 && b1 < i1);
            if (lt) { v2 = v1; v1 = a1; i1 = b1; } else if (a1 < v2) v2 = a1;
            if (a2 < v2) v2 = a2;
            if (a3 < v2) v2 = a3;
        }
        labels_out[row0 + tid] = (float)i1;
        if (v2 - v1 < M2) {
            int p = atomicAdd(&g_flagcnt, 1);
            g_flagrows[p] = row0 + tid;
            #pragma unroll
            for (int s = 0; s < 16; ++s) {
                g_cand[(size_t)p * 48 + s * 3 + 0] = (unsigned)I1[s * 128 + tid];
                g_cand[(size_t)p * 48 + s * 3 + 1] = (unsigned)I2[s * 128 + tid];
                g_cand[(size_t)p * 48 + s * 3 + 2] = (unsigned)I3[s * 128 + tid];
            }
        }
    }
}

// -------- exact fp32 rescore of flagged rows over 48 candidates --------
__global__ void __launch_bounds__(256)
cand_rescore_kernel(const float* __restrict__ emb, const float* __restrict__ centers,
                    float* __restrict__ labels_out) {
    const int lane = threadIdx.x & 31, w = threadIdx.x >> 5;
    const int cnt = g_flagcnt;
    for (int fi = blockIdx.x * 8 + w; fi < cnt; fi += gridDim.x * 8) {
        const int row = g_flagrows[fi];
        float xv[8];
        #pragma unroll
        for (int q = 0; q < 8; ++q)
            xv[q] = emb[(size_t)row * DD + q * 32 + lane];
        float best = 3.4e38f; int bi = 1 << 30;
        #pragma unroll 1
        for (int q = 0; q < 48; ++q) {
            int c = (int)g_cand[(size_t)fi * 48 + q];
            const float* cp = centers + (size_t)c * DD;
            float dot = 0.f;
            #pragma unroll
            for (int u = 0; u < 8; ++u)
                dot = fmaf(xv[u], __ldg(cp + u * 32 + lane), dot);
            #pragma unroll
            for (int o = 16; o > 0; o >>= 1) dot += __shfl_xor_sync(~0u, dot, o);
            float v = fmaf(-2.f, dot, __ldg(&g_c2[c]));
            if (v < best || (v == best && c < bi)) { best = v; bi = c; }
        }
        if (lane == 0) labels_out[row] = (float)bi;
    }
}

// -------- exact loss + segment sums + counts (final labels) --------
__global__ void __launch_bounds__(256)
scatter_kernel(const float* __restrict__ emb, const float* __restrict__ centers,
               const float* __restrict__ labels) {
    const int t = threadIdx.x;
    const int r0 = blockIdx.x * 64;
    float lsum = 0.f;
    #pragma unroll 1
    for (int r = 0; r < 64; ++r) {
        const int row = r0 + r;
        const int lab = (int)labels[row];
        float x = emb[(size_t)row * DD + t];
        float c = __ldg(&centers[(size_t)lab * DD + t]);
        float d = x - c;
        lsum = fmaf(d, d, lsum);
        atomicAdd(&g_acc[(size_t)lab * DD + t], x);
        if (t == 0) atomicAdd(&g_cntf[lab], 1.0f);
    }
    __shared__ float red[8];
    #pragma unroll
    for (int o = 16; o > 0; o >>= 1) lsum += __shfl_down_sync(~0u, lsum, o);
    if ((t & 31) == 0) red[t >> 5] = lsum;
    __syncthreads();
    if (t == 0) {
        float s = 0.f;
        #pragma unroll
        for (int w = 0; w < 8; ++w) s += red[w];
        atomicAdd(&g_loss, s);
    }
}

__global__ void finalize_kernel(float* __restrict__ out) {
    int k = blockIdx.x, d = threadIdx.x;
    float cnt = g_cntf[k];
    out[(size_t)NN + (size_t)k * DD + d] = g_acc[(size_t)k * DD + d] / cnt;
    if (d == 0) out[(size_t)NN + (size_t)KK * DD + k] = cnt;
    if (k == 0 && d == 0) out[(size_t)NN + (size_t)KK * DD + KK] = g_loss / (float)NN;
}

extern "C" void kernel_launch(void* const* d_in, const int* in_sizes, int n_in,
                              void* d_out, int out_size) {
    const float* emb     = (const float*)d_in[0];
    const float* centers = (const float*)d_in[1];
    const int*   counts  = (const int*)d_in[2];
    float* out = (float*)d_out;

    cudaFuncSetAttribute(gemm_kernel, cudaFuncAttributeMaxDynamicSharedMemorySize, GEMM_SMEM);

    init_kernel<<<KK, 256>>>(centers, counts);
    gemm_kernel<<<NN / BM, 256, GEMM_SMEM>>>(emb, out);
    cand_rescore_kernel<<<1024, 256>>>(emb, centers, out);
    scatter_kernel<<<NN / 64, 256>>>(emb, centers, out);
    finalize_kernel<<<KK, DD>>>(out);
}